// round 3
// baseline (speedup 1.0000x reference)
#include <cuda_runtime.h>
#include <cuda_bf16.h>
#include <math.h>

// Problem constants (from reference)
#define BATCH 8192
#define DIM   512
#define HID   2048
#define NSTEPS 10
#define DT 0.1f

// Scratch (allocation-free rule: __device__ globals)
__device__ float g_hidden[BATCH * HID];   // 64 MB
__device__ float g_k1[BATCH * DIM];       // 16 MB
__device__ float g_ytmp[BATCH * DIM];     // 16 MB
__device__ float g_y[BATCH * DIM];        // 16 MB

// ---------------------------------------------------------------------------
// Fused SGEMM: C = epilogue(A[MxK] @ B[KxN] + bias[N])
// EPI 0: out0 = tanh(c)                        (hidden activation)
// EPI 1: out0 = c (k1), out1 = yin + DT*c      (k1 and ytmp)
// EPI 2: out0 = yin + 0.5*DT*(k1in + c)        (Heun update)
// Tiles: 128x128x8, 256 threads, 8x8 per thread. M,N,K divisible by tiles.
// ---------------------------------------------------------------------------
template <int EPI>
__global__ __launch_bounds__(256, 2)
void gemm128(const float* __restrict__ A, const float* __restrict__ B,
             const float* __restrict__ bias, int M, int N, int K,
             const float* __restrict__ yin, const float* __restrict__ k1in,
             float* __restrict__ out0, float* __restrict__ out1)
{
    __shared__ float As[8][128];
    __shared__ float Bs[8][128];

    const int bm = blockIdx.y * 128;
    const int bn = blockIdx.x * 128;
    const int tid = threadIdx.x;
    const int ty = tid >> 4;          // 0..15
    const int tx = tid & 15;          // 0..15

    // Global load mapping
    const int arow = tid >> 1;            // 0..127
    const int acol = (tid & 1) * 4;       // 0 or 4
    const int brow = tid >> 5;            // 0..7
    const int bcol = (tid & 31) * 4;      // 0..124

    const float* Aptr = A + (size_t)(bm + arow) * K + acol;
    const float* Bptr = B + (size_t)brow * N + bn + bcol;

    float acc[8][8];
#pragma unroll
    for (int i = 0; i < 8; i++)
#pragma unroll
        for (int j = 0; j < 8; j++) acc[i][j] = 0.f;

    for (int k0 = 0; k0 < K; k0 += 8) {
        float4 av = *(const float4*)(Aptr + k0);
        float4 bv = *(const float4*)(Bptr + (size_t)k0 * N);
        __syncthreads();
        As[acol + 0][arow] = av.x;
        As[acol + 1][arow] = av.y;
        As[acol + 2][arow] = av.z;
        As[acol + 3][arow] = av.w;
        *(float4*)&Bs[brow][bcol] = bv;
        __syncthreads();

#pragma unroll
        for (int kk = 0; kk < 8; kk++) {
            float ar[8], br[8];
            *(float4*)(ar)     = *(const float4*)&As[kk][ty * 8];
            *(float4*)(ar + 4) = *(const float4*)&As[kk][ty * 8 + 4];
            *(float4*)(br)     = *(const float4*)&Bs[kk][tx * 8];
            *(float4*)(br + 4) = *(const float4*)&Bs[kk][tx * 8 + 4];
#pragma unroll
            for (int i = 0; i < 8; i++)
#pragma unroll
                for (int j = 0; j < 8; j++)
                    acc[i][j] = fmaf(ar[i], br[j], acc[i][j]);
        }
    }

    // Epilogue
    float bvs[8];
#pragma unroll
    for (int j = 0; j < 8; j++) bvs[j] = bias[bn + tx * 8 + j];

#pragma unroll
    for (int i = 0; i < 8; i++) {
        const int row = bm + ty * 8 + i;
        const size_t base = (size_t)row * N + bn + tx * 8;
#pragma unroll
        for (int j = 0; j < 8; j++) {
            float c = acc[i][j] + bvs[j];
            const size_t idx = base + j;
            if (EPI == 0) {
                out0[idx] = tanhf(c);
            } else if (EPI == 1) {
                out0[idx] = c;                      // k1
                out1[idx] = yin[idx] + DT * c;      // ytmp = y + dt*k1
            } else {
                out0[idx] = yin[idx] + (0.5f * DT) * (k1in[idx] + c);
            }
        }
    }
}

extern "C" void kernel_launch(void* const* d_in, const int* in_sizes, int n_in,
                              void* d_out, int out_size)
{
    const float* y0 = (const float*)d_in[0];
    const float* W1 = (const float*)d_in[1];
    const float* b1 = (const float*)d_in[2];
    const float* W2 = (const float*)d_in[3];
    const float* b2 = (const float*)d_in[4];
    float* yout = (float*)d_out;

    float *hidden, *k1, *ytmp, *ybuf;
    cudaGetSymbolAddress((void**)&hidden, g_hidden);
    cudaGetSymbolAddress((void**)&k1,     g_k1);
    cudaGetSymbolAddress((void**)&ytmp,   g_ytmp);
    cudaGetSymbolAddress((void**)&ybuf,   g_y);

    dim3 g1(HID / 128, BATCH / 128);   // GEMM1: [B,D]@[D,H]
    dim3 g2(DIM / 128, BATCH / 128);   // GEMM2: [B,H]@[H,D]

    const float* ycur = y0;
    for (int s = 0; s < NSTEPS; s++) {
        // k1 = f(y):   hidden = tanh(y@W1+b1); k1 = hidden@W2+b2; ytmp = y+dt*k1
        gemm128<0><<<g1, 256>>>(ycur,   W1, b1, BATCH, HID, DIM, nullptr, nullptr, hidden, nullptr);
        gemm128<1><<<g2, 256>>>(hidden, W2, b2, BATCH, DIM, HID, ycur,    nullptr, k1,     ytmp);
        // k2 = f(ytmp); y = y + 0.5*dt*(k1+k2)
        gemm128<0><<<g1, 256>>>(ytmp,   W1, b1, BATCH, HID, DIM, nullptr, nullptr, hidden, nullptr);
        float* ynext = (s == NSTEPS - 1) ? yout : ybuf;
        gemm128<2><<<g2, 256>>>(hidden, W2, b2, BATCH, DIM, HID, ycur,    k1,      ynext,  nullptr);
        ycur = ybuf;
    }
}

// round 6
// speedup vs baseline: 5.0068x; 5.0068x over previous
#include <cuda_runtime.h>
#include <cuda_bf16.h>
#include <cstdint>
#include <math.h>

#define BATCH 8192
#define DIM   512
#define HID   2048
#define NSTEPS 10

// ---------------- tile config ----------------
#define BM 128
#define BN 128
#define BK 64                        // K elems per stage (64 bf16 = 128B rows)
#define STAGE 65536                  // Ah 16K + Al 16K + Bh 16K + Bl 16K
#define NSTAGE 3
#define SMEM_DYN (NSTAGE * STAGE + 1024)

// ---------------- scratch (__device__ globals; allocation-free rule) ----------------
__device__ __align__(16) __nv_bfloat16 g_hidh[(size_t)BATCH * HID];
__device__ __align__(16) __nv_bfloat16 g_hidl[(size_t)BATCH * HID];
__device__ __align__(16) __nv_bfloat16 g_yhi [(size_t)BATCH * DIM];
__device__ __align__(16) __nv_bfloat16 g_ylo [(size_t)BATCH * DIM];
__device__ __align__(16) __nv_bfloat16 g_yth [(size_t)BATCH * DIM];
__device__ __align__(16) __nv_bfloat16 g_ytl [(size_t)BATCH * DIM];
__device__ __align__(16) float         g_k1  [(size_t)BATCH * DIM];
__device__ __align__(16) float         g_yf  [(size_t)BATCH * DIM];
__device__ __align__(16) __nv_bfloat16 g_w1h [(size_t)DIM * HID];  // W1^T [HID,DIM] K-major
__device__ __align__(16) __nv_bfloat16 g_w1l [(size_t)DIM * HID];
__device__ __align__(16) __nv_bfloat16 g_w2h [(size_t)HID * DIM];  // W2^T [DIM,HID] K-major
__device__ __align__(16) __nv_bfloat16 g_w2l [(size_t)HID * DIM];

// ---------------- helpers (baseline PTX only: sm_80-class ops) ----------------
__device__ __forceinline__ uint32_t smem_u32(const void* p) {
    uint32_t a;
    asm("{ .reg .u64 t; cvta.to.shared.u64 t, %1; cvt.u32.u64 %0, t; }" : "=r"(a) : "l"(p));
    return a;
}
#define SWZ(o) ((uint32_t)(o) ^ ((((uint32_t)(o)) >> 3) & 0x70u))

__device__ __forceinline__ void cp16(uint32_t s, const void* g) {
    asm volatile("cp.async.cg.shared.global [%0], [%1], 16;" :: "r"(s), "l"(g));
}
#define CP_COMMIT() asm volatile("cp.async.commit_group;" ::: "memory")
#define CP_WAIT(n)  asm volatile("cp.async.wait_group %0;" :: "n"(n) : "memory")

__device__ __forceinline__ void ldsm4(uint32_t& r0, uint32_t& r1, uint32_t& r2, uint32_t& r3,
                                      uint32_t addr) {
    asm volatile("ldmatrix.sync.aligned.m8n8.x4.shared.b16 {%0,%1,%2,%3}, [%4];"
                 : "=r"(r0), "=r"(r1), "=r"(r2), "=r"(r3) : "r"(addr));
}
__device__ __forceinline__ void mma16816(float* c, const uint32_t* a, const uint32_t* b) {
    asm volatile("mma.sync.aligned.m16n8k16.row.col.f32.bf16.bf16.f32 "
                 "{%0,%1,%2,%3}, {%4,%5,%6,%7}, {%8,%9}, {%0,%1,%2,%3};"
                 : "+f"(c[0]), "+f"(c[1]), "+f"(c[2]), "+f"(c[3])
                 : "r"(a[0]), "r"(a[1]), "r"(a[2]), "r"(a[3]), "r"(b[0]), "r"(b[1]));
}

// ---------------- stage loader: 4 tiles of [128 rows x 128B], 256 threads ----------------
__device__ __forceinline__ void load_stage(
    uint32_t st,
    const __nv_bfloat16* __restrict__ Ahi, const __nv_bfloat16* __restrict__ Alo,
    const __nv_bfloat16* __restrict__ Bhi, const __nv_bfloat16* __restrict__ Blo,
    int bm, int bn, int K, int kc0, int tid)
{
#pragma unroll
    for (int i = 0; i < 4; i++) {
        const int lin = i * 256 + tid;
        const int row = lin >> 3;
        const uint32_t q16 = (uint32_t)(lin & 7) * 16u;
        const uint32_t so = SWZ((uint32_t)row * 128u + q16);
        const size_t offA = ((size_t)(bm + row) * K + kc0) * 2 + q16;
        const size_t offB = ((size_t)(bn + row) * K + kc0) * 2 + q16;
        cp16(st + so,          (const char*)Ahi + offA);
        cp16(st + 16384u + so, (const char*)Alo + offA);
        cp16(st + 32768u + so, (const char*)Bhi + offB);
        cp16(st + 49152u + so, (const char*)Blo + offB);
    }
    CP_COMMIT();
}

// ---------------- fused split-bf16 HMMA GEMM ----------------
// C[M,N] = (Ah+Al) @ (Bh+Bl)^T + bias   (ll term dropped, ~2^-32)
//  EPI 0: v = tanh(c)                   -> (ohi,olo)
//  EPI 1: outf = c (k1);  v = yin+0.1c  -> (ohi,olo)
//  EPI 2: v = yin+0.05(k1in+c); outf=v  -> (ohi,olo)
template <int EPI>
__global__ void __launch_bounds__(256) ode_gemm(
    const __nv_bfloat16* __restrict__ Ahi, const __nv_bfloat16* __restrict__ Alo,
    const __nv_bfloat16* __restrict__ Bhi, const __nv_bfloat16* __restrict__ Blo,
    const float* __restrict__ bias, int N, int K,
    const float* __restrict__ yin, const float* __restrict__ k1in,
    float* __restrict__ outf,
    __nv_bfloat16* __restrict__ ohi, __nv_bfloat16* __restrict__ olo)
{
    extern __shared__ char dyn[];
    const uint32_t sb = (smem_u32(dyn) + 1023u) & ~1023u;

    const int tid = threadIdx.x;
    const int wid = tid >> 5, lane = tid & 31;
    const int warp_m = wid >> 2, warp_n = wid & 3;     // 2 x 4 warps, 64x32 warp tile
    const int bm = blockIdx.y * BM, bn = blockIdx.x * BN;

    float acc[4][4][4];
#pragma unroll
    for (int mt = 0; mt < 4; mt++)
#pragma unroll
        for (int nt = 0; nt < 4; nt++)
#pragma unroll
            for (int r = 0; r < 4; r++) acc[mt][nt][r] = 0.f;

    const int nit = K >> 6;
    load_stage(sb,         Ahi, Alo, Bhi, Blo, bm, bn, K, 0,  tid);
    load_stage(sb + STAGE, Ahi, Alo, Bhi, Blo, bm, bn, K, BK, tid);

    // per-lane ldmatrix byte offsets (within a tile, before swizzle)
    const uint32_t aOff = (uint32_t)(warp_m * 64 + (lane & 15)) * 128u + (uint32_t)(lane >> 4) * 16u;
    const uint32_t bOff = (uint32_t)(warp_n * 32 + (lane & 7) + ((lane >> 4) << 3)) * 128u
                        + (uint32_t)((lane >> 3) & 1) * 16u;

#pragma unroll 1
    for (int c = 0; c < nit; c++) {
        if (c + 1 < nit) CP_WAIT(1); else CP_WAIT(0);
        __syncthreads();
        if (c + 2 < nit)
            load_stage(sb + (uint32_t)((c + 2) % NSTAGE) * STAGE,
                       Ahi, Alo, Bhi, Blo, bm, bn, K, (c + 2) * BK, tid);

        const uint32_t st = sb + (uint32_t)(c % NSTAGE) * STAGE;
#pragma unroll
        for (int ks = 0; ks < 4; ks++) {
            uint32_t ah[4][4], al[4][4], bh[2][4], bl[2][4];
#pragma unroll
            for (int mt = 0; mt < 4; mt++) {
                const uint32_t o = SWZ(aOff + (uint32_t)mt * 2048u + (uint32_t)ks * 32u);
                ldsm4(ah[mt][0], ah[mt][1], ah[mt][2], ah[mt][3], st + o);
                ldsm4(al[mt][0], al[mt][1], al[mt][2], al[mt][3], st + 16384u + o);
            }
#pragma unroll
            for (int nb = 0; nb < 2; nb++) {
                const uint32_t o = SWZ(bOff + (uint32_t)nb * 2048u + (uint32_t)ks * 32u);
                ldsm4(bh[nb][0], bh[nb][1], bh[nb][2], bh[nb][3], st + 32768u + o);
                ldsm4(bl[nb][0], bl[nb][1], bl[nb][2], bl[nb][3], st + 49152u + o);
            }
#pragma unroll
            for (int mt = 0; mt < 4; mt++)
#pragma unroll
                for (int nt = 0; nt < 4; nt++) {
                    float* cc = acc[mt][nt];
                    const uint32_t* ph = &bh[nt >> 1][(nt & 1) * 2];
                    const uint32_t* pl = &bl[nt >> 1][(nt & 1) * 2];
                    mma16816(cc, ah[mt], ph);   // hi*hi
                    mma16816(cc, ah[mt], pl);   // hi*lo
                    mma16816(cc, al[mt], ph);   // lo*hi
                }
        }
    }

    // ---------------- epilogue from register accumulators ----------------
    const int row0 = bm + warp_m * 64 + (lane >> 2);
    const int col0 = bn + warp_n * 32 + (lane & 3) * 2;
#pragma unroll
    for (int mt = 0; mt < 4; mt++)
#pragma unroll
        for (int nt = 0; nt < 4; nt++) {
            const int ccol = col0 + nt * 8;
            const float2 bv = *(const float2*)(bias + ccol);
#pragma unroll
            for (int h = 0; h < 2; h++) {
                const int r = row0 + mt * 16 + 8 * h;
                const size_t idx = (size_t)r * N + ccol;
                float x0 = acc[mt][nt][2 * h]     + bv.x;
                float x1 = acc[mt][nt][2 * h + 1] + bv.y;
                float v0, v1;
                if (EPI == 0) {
                    const float e0 = __expf(2.0f * x0);
                    const float e1 = __expf(2.0f * x1);
                    v0 = 1.0f - __fdividef(2.0f, e0 + 1.0f);
                    v1 = 1.0f - __fdividef(2.0f, e1 + 1.0f);
                } else if (EPI == 1) {
                    *(float2*)(outf + idx) = make_float2(x0, x1);
                    const float2 yv = *(const float2*)(yin + idx);
                    v0 = yv.x + 0.1f * x0;
                    v1 = yv.y + 0.1f * x1;
                } else {
                    const float2 yv = *(const float2*)(yin + idx);
                    const float2 kv = *(const float2*)(k1in + idx);
                    v0 = yv.x + 0.05f * (kv.x + x0);
                    v1 = yv.y + 0.05f * (kv.y + x1);
                    *(float2*)(outf + idx) = make_float2(v0, v1);
                }
                const __nv_bfloat16 h0 = __float2bfloat16(v0);
                const __nv_bfloat16 h1 = __float2bfloat16(v1);
                __nv_bfloat162 hp; hp.x = h0; hp.y = h1;
                __nv_bfloat162 lp;
                lp.x = __float2bfloat16(v0 - __bfloat162float(h0));
                lp.y = __float2bfloat16(v1 - __bfloat162float(h1));
                *(__nv_bfloat162*)(ohi + idx) = hp;
                *(__nv_bfloat162*)(olo + idx) = lp;
            }
        }
}

// ---------------- conversion kernels ----------------
__global__ void split_f32(const float* __restrict__ x,
                          __nv_bfloat16* __restrict__ hi, __nv_bfloat16* __restrict__ lo, int n)
{
    int i = blockIdx.x * blockDim.x + threadIdx.x;
    if (i < n) {
        float v = x[i];
        __nv_bfloat16 h = __float2bfloat16(v);
        hi[i] = h;
        lo[i] = __float2bfloat16(v - __bfloat162float(h));
    }
}

// W[K,N] row-major -> Wt[N,K] split bf16 (K-major B operand)
__global__ void transpose_split(const float* __restrict__ W, int K, int N,
                                __nv_bfloat16* __restrict__ hi, __nv_bfloat16* __restrict__ lo)
{
    __shared__ float t[32][33];
    const int nx = blockIdx.x * 32 + threadIdx.x;
    const int ky = blockIdx.y * 32 + threadIdx.y;
#pragma unroll
    for (int i = 0; i < 32; i += 8)
        t[threadIdx.y + i][threadIdx.x] = W[(size_t)(ky + i) * N + nx];
    __syncthreads();
    const int on = blockIdx.x * 32 + threadIdx.y;
    const int ok = blockIdx.y * 32 + threadIdx.x;
#pragma unroll
    for (int i = 0; i < 32; i += 8) {
        float v = t[threadIdx.x][threadIdx.y + i];
        __nv_bfloat16 h = __float2bfloat16(v);
        size_t idx = (size_t)(on + i) * K + ok;
        hi[idx] = h;
        lo[idx] = __float2bfloat16(v - __bfloat162float(h));
    }
}

// ---------------- host ----------------
extern "C" void kernel_launch(void* const* d_in, const int* in_sizes, int n_in,
                              void* d_out, int out_size)
{
    const float* y0 = (const float*)d_in[0];
    const float* W1 = (const float*)d_in[1];
    const float* b1 = (const float*)d_in[2];
    const float* W2 = (const float*)d_in[3];
    const float* b2 = (const float*)d_in[4];
    float* yout = (float*)d_out;

    __nv_bfloat16 *hidh, *hidl, *yhi, *ylo, *yth, *ytl, *w1h, *w1l, *w2h, *w2l;
    float *k1f, *yf;
    cudaGetSymbolAddress((void**)&hidh, g_hidh);
    cudaGetSymbolAddress((void**)&hidl, g_hidl);
    cudaGetSymbolAddress((void**)&yhi,  g_yhi);
    cudaGetSymbolAddress((void**)&ylo,  g_ylo);
    cudaGetSymbolAddress((void**)&yth,  g_yth);
    cudaGetSymbolAddress((void**)&ytl,  g_ytl);
    cudaGetSymbolAddress((void**)&k1f,  g_k1);
    cudaGetSymbolAddress((void**)&yf,   g_yf);
    cudaGetSymbolAddress((void**)&w1h,  g_w1h);
    cudaGetSymbolAddress((void**)&w1l,  g_w1l);
    cudaGetSymbolAddress((void**)&w2h,  g_w2h);
    cudaGetSymbolAddress((void**)&w2l,  g_w2l);

    cudaFuncSetAttribute(ode_gemm<0>, cudaFuncAttributeMaxDynamicSharedMemorySize, SMEM_DYN);
    cudaFuncSetAttribute(ode_gemm<1>, cudaFuncAttributeMaxDynamicSharedMemorySize, SMEM_DYN);
    cudaFuncSetAttribute(ode_gemm<2>, cudaFuncAttributeMaxDynamicSharedMemorySize, SMEM_DYN);

    split_f32<<<(BATCH * DIM + 255) / 256, 256>>>(y0, yhi, ylo, BATCH * DIM);
    transpose_split<<<dim3(HID / 32, DIM / 32), dim3(32, 8)>>>(W1, DIM, HID, w1h, w1l);
    transpose_split<<<dim3(DIM / 32, HID / 32), dim3(32, 8)>>>(W2, HID, DIM, w2h, w2l);

    const dim3 g1(HID / BN, BATCH / BM);   // (16, 64)
    const dim3 g2(DIM / BN, BATCH / BM);   // (4, 64)

    const float* ycur = y0;
    for (int s = 0; s < NSTEPS; s++) {
        // k1 = f(y): hidden = tanh(y@W1+b1); k1 = hidden@W2+b2; ytmp = y + dt*k1
        ode_gemm<0><<<g1, 256, SMEM_DYN>>>(yhi, ylo, w1h, w1l, b1, HID, DIM,
                                           nullptr, nullptr, nullptr, hidh, hidl);
        ode_gemm<1><<<g2, 256, SMEM_DYN>>>(hidh, hidl, w2h, w2l, b2, DIM, HID,
                                           ycur, nullptr, k1f, yth, ytl);
        // k2 = f(ytmp); y = y + 0.5*dt*(k1+k2)
        ode_gemm<0><<<g1, 256, SMEM_DYN>>>(yth, ytl, w1h, w1l, b1, HID, DIM,
                                           nullptr, nullptr, nullptr, hidh, hidl);
        float* of = (s == NSTEPS - 1) ? yout : yf;
        ode_gemm<2><<<g2, 256, SMEM_DYN>>>(hidh, hidl, w2h, w2l, b2, DIM, HID,
                                           ycur, k1f, of, yhi, ylo);
        ycur = yf;
    }
}

// round 8
// speedup vs baseline: 7.6365x; 1.5252x over previous
#include <cuda_runtime.h>
#include <cuda_fp16.h>
#include <cstdint>
#include <math.h>

#define BATCH 8192
#define DIM   512
#define HID   2048
#define NSTEPS 10

// ---------------- tile config ----------------
#define BM 128
#define BN 128
#define BK 64                        // K elems per stage (64 fp16 = 128B rows)
#define STAGE 49152                  // A 16K + Wh 16K + Wl 16K
#define NSTAGE 2
#define SMEM_DYN (NSTAGE * STAGE + 1024)

// ---------------- scratch (__device__ globals; allocation-free rule) ----------------
__device__ __align__(16) __half g_hid16[(size_t)BATCH * HID];   // tanh activations
__device__ __align__(16) __half g_y16  [(size_t)BATCH * DIM];   // y (fp16 view)
__device__ __align__(16) __half g_yt16 [(size_t)BATCH * DIM];   // ytmp (fp16 view)
__device__ __align__(16) float  g_k1   [(size_t)BATCH * DIM];
__device__ __align__(16) float  g_yf   [(size_t)BATCH * DIM];   // y state fp32
__device__ __align__(16) __half g_w1h  [(size_t)DIM * HID];     // W1^T [HID,DIM] K-major
__device__ __align__(16) __half g_w1l  [(size_t)DIM * HID];
__device__ __align__(16) __half g_w2h  [(size_t)HID * DIM];     // W2^T [DIM,HID] K-major
__device__ __align__(16) __half g_w2l  [(size_t)HID * DIM];

// ---------------- helpers (baseline PTX only; no sm_*a features) ----------------
__device__ __forceinline__ uint32_t smem_u32(const void* p) {
    uint32_t a;
    asm("{ .reg .u64 t; cvta.to.shared.u64 t, %1; cvt.u32.u64 %0, t; }" : "=r"(a) : "l"(p));
    return a;
}
#define SWZ(o) ((uint32_t)(o) ^ ((((uint32_t)(o)) >> 3) & 0x70u))

__device__ __forceinline__ void cp16(uint32_t s, const void* g) {
    asm volatile("cp.async.cg.shared.global [%0], [%1], 16;" :: "r"(s), "l"(g));
}
#define CP_COMMIT() asm volatile("cp.async.commit_group;" ::: "memory")
#define CP_WAIT(n)  asm volatile("cp.async.wait_group %0;" :: "n"(n) : "memory")

__device__ __forceinline__ void ldsm4(uint32_t& r0, uint32_t& r1, uint32_t& r2, uint32_t& r3,
                                      uint32_t addr) {
    asm volatile("ldmatrix.sync.aligned.m8n8.x4.shared.b16 {%0,%1,%2,%3}, [%4];"
                 : "=r"(r0), "=r"(r1), "=r"(r2), "=r"(r3) : "r"(addr));
}
__device__ __forceinline__ void mma16816h(float* c, const uint32_t* a, const uint32_t* b) {
    asm volatile("mma.sync.aligned.m16n8k16.row.col.f32.f16.f16.f32 "
                 "{%0,%1,%2,%3}, {%4,%5,%6,%7}, {%8,%9}, {%0,%1,%2,%3};"
                 : "+f"(c[0]), "+f"(c[1]), "+f"(c[2]), "+f"(c[3])
                 : "r"(a[0]), "r"(a[1]), "r"(a[2]), "r"(a[3]), "r"(b[0]), "r"(b[1]));
}

// ---------------- stage loader: 3 tiles of [128 rows x 128B], 256 threads ----------------
__device__ __forceinline__ void load_stage(
    uint32_t st,
    const __half* __restrict__ A, const __half* __restrict__ Wh, const __half* __restrict__ Wl,
    int bm, int bn, int K, int kc0, int tid)
{
#pragma unroll
    for (int i = 0; i < 4; i++) {
        const int lin = i * 256 + tid;
        const int row = lin >> 3;
        const uint32_t q16 = (uint32_t)(lin & 7) * 16u;
        const uint32_t so = SWZ((uint32_t)row * 128u + q16);
        const size_t offA = ((size_t)(bm + row) * K + kc0) * 2 + q16;
        const size_t offB = ((size_t)(bn + row) * K + kc0) * 2 + q16;
        cp16(st + so,          (const char*)A  + offA);
        cp16(st + 16384u + so, (const char*)Wh + offB);
        cp16(st + 32768u + so, (const char*)Wl + offB);
    }
    CP_COMMIT();
}

// ---------------- fused fp16 HMMA GEMM: C = A @ (Wh+Wl)^T + bias ----------------
//  EPI 0: v = tanh(c)                      -> oh (fp16)
//  EPI 1: outf = c (k1);  v = yin+0.1c     -> oh (fp16 ytmp)
//  EPI 2: v = yin+0.05(k1in+c); outf = v   -> oh (fp16 y_next)
template <int EPI>
__global__ void __launch_bounds__(256, 2) ode_gemm(
    const __half* __restrict__ A,
    const __half* __restrict__ Wh, const __half* __restrict__ Wl,
    const float* __restrict__ bias, int N, int K,
    const float* __restrict__ yin, const float* __restrict__ k1in,
    float* __restrict__ outf, __half* __restrict__ oh)
{
    extern __shared__ char dyn[];
    const uint32_t sb = (smem_u32(dyn) + 1023u) & ~1023u;

    const int tid = threadIdx.x;
    const int wid = tid >> 5, lane = tid & 31;
    const int warp_m = wid >> 2, warp_n = wid & 3;     // 2 x 4 warps, 64x32 warp tile
    const int bm = blockIdx.y * BM, bn = blockIdx.x * BN;

    float acc[4][4][4];
#pragma unroll
    for (int mt = 0; mt < 4; mt++)
#pragma unroll
        for (int nt = 0; nt < 4; nt++)
#pragma unroll
            for (int r = 0; r < 4; r++) acc[mt][nt][r] = 0.f;

    const int nit = K >> 6;
    load_stage(sb,         A, Wh, Wl, bm, bn, K, 0,  tid);
    load_stage(sb + STAGE, A, Wh, Wl, bm, bn, K, BK, tid);

    // per-lane ldmatrix byte offsets (pre-swizzle), identical geometry to round-6
    const uint32_t aOff = (uint32_t)(warp_m * 64 + (lane & 15)) * 128u + (uint32_t)(lane >> 4) * 16u;
    const uint32_t bOff = (uint32_t)(warp_n * 32 + (lane & 7) + ((lane >> 4) << 3)) * 128u
                        + (uint32_t)((lane >> 3) & 1) * 16u;

#pragma unroll 1
    for (int c = 0; c < nit; c++) {
        if (c + 1 < nit) CP_WAIT(1); else CP_WAIT(0);
        __syncthreads();

        const uint32_t st = sb + (uint32_t)(c & 1) * STAGE;
#pragma unroll
        for (int ks = 0; ks < 4; ks++) {
            uint32_t ah[4][4], bh[2][4], bl[2][4];
#pragma unroll
            for (int mt = 0; mt < 4; mt++) {
                const uint32_t o = SWZ(aOff + (uint32_t)mt * 2048u + (uint32_t)ks * 32u);
                ldsm4(ah[mt][0], ah[mt][1], ah[mt][2], ah[mt][3], st + o);
            }
#pragma unroll
            for (int nb = 0; nb < 2; nb++) {
                const uint32_t o = SWZ(bOff + (uint32_t)nb * 2048u + (uint32_t)ks * 32u);
                ldsm4(bh[nb][0], bh[nb][1], bh[nb][2], bh[nb][3], st + 16384u + o);
                ldsm4(bl[nb][0], bl[nb][1], bl[nb][2], bl[nb][3], st + 32768u + o);
            }
#pragma unroll
            for (int mt = 0; mt < 4; mt++)
#pragma unroll
                for (int nt = 0; nt < 4; nt++) {
                    float* cc = acc[mt][nt];
                    mma16816h(cc, ah[mt], &bh[nt >> 1][(nt & 1) * 2]);   // A * Wh
                    mma16816h(cc, ah[mt], &bl[nt >> 1][(nt & 1) * 2]);   // A * Wl
                }
        }
        __syncthreads();
        if (c + 2 < nit)
            load_stage(sb + (uint32_t)(c & 1) * STAGE, A, Wh, Wl, bm, bn, K, (c + 2) * BK, tid);
    }

    // ---------------- epilogue from register accumulators ----------------
    const int row0 = bm + warp_m * 64 + (lane >> 2);
    const int col0 = bn + warp_n * 32 + (lane & 3) * 2;
#pragma unroll
    for (int mt = 0; mt < 4; mt++)
#pragma unroll
        for (int nt = 0; nt < 4; nt++) {
            const int ccol = col0 + nt * 8;
            const float2 bv = *(const float2*)(bias + ccol);
#pragma unroll
            for (int h = 0; h < 2; h++) {
                const int r = row0 + mt * 16 + 8 * h;
                const size_t idx = (size_t)r * N + ccol;
                float x0 = acc[mt][nt][2 * h]     + bv.x;
                float x1 = acc[mt][nt][2 * h + 1] + bv.y;
                float v0, v1;
                if (EPI == 0) {
                    const float e0 = __expf(2.0f * x0);
                    const float e1 = __expf(2.0f * x1);
                    v0 = 1.0f - __fdividef(2.0f, e0 + 1.0f);
                    v1 = 1.0f - __fdividef(2.0f, e1 + 1.0f);
                } else if (EPI == 1) {
                    *(float2*)(outf + idx) = make_float2(x0, x1);
                    const float2 yv = *(const float2*)(yin + idx);
                    v0 = yv.x + 0.1f * x0;
                    v1 = yv.y + 0.1f * x1;
                } else {
                    const float2 yv = *(const float2*)(yin + idx);
                    const float2 kv = *(const float2*)(k1in + idx);
                    v0 = yv.x + 0.05f * (kv.x + x0);
                    v1 = yv.y + 0.05f * (kv.y + x1);
                    *(float2*)(outf + idx) = make_float2(v0, v1);
                }
                *(__half2*)(oh + idx) = __floats2half2_rn(v0, v1);
            }
        }
}

// ---------------- conversion kernels ----------------
__global__ void to_f16(const float* __restrict__ x, __half* __restrict__ o, int n)
{
    int i = blockIdx.x * blockDim.x + threadIdx.x;
    if (i < n) o[i] = __float2half(x[i]);
}

// W[K,N] row-major -> Wt[N,K] split fp16 hi/lo (K-major B operand)
__global__ void transpose_split(const float* __restrict__ W, int K, int N,
                                __half* __restrict__ hi, __half* __restrict__ lo)
{
    __shared__ float t[32][33];
    const int nx = blockIdx.x * 32 + threadIdx.x;
    const int ky = blockIdx.y * 32 + threadIdx.y;
#pragma unroll
    for (int i = 0; i < 32; i += 8)
        t[threadIdx.y + i][threadIdx.x] = W[(size_t)(ky + i) * N + nx];
    __syncthreads();
    const int on = blockIdx.x * 32 + threadIdx.y;
    const int ok = blockIdx.y * 32 + threadIdx.x;
#pragma unroll
    for (int i = 0; i < 32; i += 8) {
        float v = t[threadIdx.x][threadIdx.y + i];
        __half h = __float2half(v);
        size_t idx = (size_t)(on + i) * K + ok;
        hi[idx] = h;
        lo[idx] = __float2half(v - __half2float(h));   // subnormal-range residual: ok
    }
}

// ---------------- host ----------------
extern "C" void kernel_launch(void* const* d_in, const int* in_sizes, int n_in,
                              void* d_out, int out_size)
{
    const float* y0 = (const float*)d_in[0];
    const float* W1 = (const float*)d_in[1];
    const float* b1 = (const float*)d_in[2];
    const float* W2 = (const float*)d_in[3];
    const float* b2 = (const float*)d_in[4];
    float* yout = (float*)d_out;

    __half *hid16, *y16, *yt16, *w1h, *w1l, *w2h, *w2l;
    float *k1f, *yf;
    cudaGetSymbolAddress((void**)&hid16, g_hid16);
    cudaGetSymbolAddress((void**)&y16,   g_y16);
    cudaGetSymbolAddress((void**)&yt16,  g_yt16);
    cudaGetSymbolAddress((void**)&k1f,   g_k1);
    cudaGetSymbolAddress((void**)&yf,    g_yf);
    cudaGetSymbolAddress((void**)&w1h,   g_w1h);
    cudaGetSymbolAddress((void**)&w1l,   g_w1l);
    cudaGetSymbolAddress((void**)&w2h,   g_w2h);
    cudaGetSymbolAddress((void**)&w2l,   g_w2l);

    cudaFuncSetAttribute(ode_gemm<0>, cudaFuncAttributeMaxDynamicSharedMemorySize, SMEM_DYN);
    cudaFuncSetAttribute(ode_gemm<1>, cudaFuncAttributeMaxDynamicSharedMemorySize, SMEM_DYN);
    cudaFuncSetAttribute(ode_gemm<2>, cudaFuncAttributeMaxDynamicSharedMemorySize, SMEM_DYN);

    to_f16<<<(BATCH * DIM + 255) / 256, 256>>>(y0, y16, BATCH * DIM);
    transpose_split<<<dim3(HID / 32, DIM / 32), dim3(32, 8)>>>(W1, DIM, HID, w1h, w1l);
    transpose_split<<<dim3(DIM / 32, HID / 32), dim3(32, 8)>>>(W2, HID, DIM, w2h, w2l);

    const dim3 g1(HID / BN, BATCH / BM);   // (16, 64)
    const dim3 g2(DIM / BN, BATCH / BM);   // (4, 64)  -> single wave at 2 CTAs/SM

    const float* ycur = y0;
    for (int s = 0; s < NSTEPS; s++) {
        // k1 = f(y): hidden = tanh(y@W1+b1); k1 = hidden@W2+b2; ytmp = y + dt*k1
        ode_gemm<0><<<g1, 256, SMEM_DYN>>>(y16, w1h, w1l, b1, HID, DIM,
                                           nullptr, nullptr, nullptr, hid16);
        ode_gemm<1><<<g2, 256, SMEM_DYN>>>(hid16, w2h, w2l, b2, DIM, HID,
                                           ycur, nullptr, k1f, yt16);
        // k2 = f(ytmp); y = y + 0.5*dt*(k1+k2)
        ode_gemm<0><<<g1, 256, SMEM_DYN>>>(yt16, w1h, w1l, b1, HID, DIM,
                                           nullptr, nullptr, nullptr, hid16);
        float* of = (s == NSTEPS - 1) ? yout : yf;
        ode_gemm<2><<<g2, 256, SMEM_DYN>>>(hid16, w2h, w2l, b2, DIM, HID,
                                           ycur, k1f, of, y16);
        ycur = yf;
    }
}

// round 10
// speedup vs baseline: 12.9513x; 1.6960x over previous
#include <cuda_runtime.h>
#include <cuda_fp16.h>
#include <cstdint>
#include <math.h>

#define BATCH 8192
#define DIM   512
#define HID   2048
#define NSTEPS 10

// ---------------- tile config ----------------
#define BM 128
#define BN 128
#define BK 64                        // K elems per stage (64 fp16 = 128B rows)
#define STAGE 32768                  // A 16K + W 16K
#define NSTAGE 3
#define SMEM_DYN (NSTAGE * STAGE + 1024)

// ---------------- scratch (__device__ globals; allocation-free rule) ----------------
__device__ __align__(16) __half g_hid16[(size_t)BATCH * HID];   // tanh activations
__device__ __align__(16) __half g_y16  [(size_t)BATCH * DIM];   // y (fp16 view)
__device__ __align__(16) __half g_yt16 [(size_t)BATCH * DIM];   // ytmp (fp16 view)
__device__ __align__(16) float  g_k1   [(size_t)BATCH * DIM];
__device__ __align__(16) float  g_yf   [(size_t)BATCH * DIM];   // y state fp32
__device__ __align__(16) __half g_w1t  [(size_t)DIM * HID];     // W1^T [HID,DIM] K-major
__device__ __align__(16) __half g_w2t  [(size_t)HID * DIM];     // W2^T [DIM,HID] K-major

// ---------------- helpers (baseline PTX only; no sm_*a features) ----------------
__device__ __forceinline__ uint32_t smem_u32(const void* p) {
    uint32_t a;
    asm("{ .reg .u64 t; cvta.to.shared.u64 t, %1; cvt.u32.u64 %0, t; }" : "=r"(a) : "l"(p));
    return a;
}
#define SWZ(o) ((uint32_t)(o) ^ ((((uint32_t)(o)) >> 3) & 0x70u))

__device__ __forceinline__ void cp16(uint32_t s, const void* g) {
    asm volatile("cp.async.cg.shared.global [%0], [%1], 16;" :: "r"(s), "l"(g));
}
#define CP_COMMIT() asm volatile("cp.async.commit_group;" ::: "memory")
#define CP_WAIT(n)  asm volatile("cp.async.wait_group %0;" :: "n"(n) : "memory")

__device__ __forceinline__ void ldsm4(uint32_t& r0, uint32_t& r1, uint32_t& r2, uint32_t& r3,
                                      uint32_t addr) {
    asm volatile("ldmatrix.sync.aligned.m8n8.x4.shared.b16 {%0,%1,%2,%3}, [%4];"
                 : "=r"(r0), "=r"(r1), "=r"(r2), "=r"(r3) : "r"(addr));
}
__device__ __forceinline__ void mma16816h(float* c, const uint32_t* a, const uint32_t* b) {
    asm volatile("mma.sync.aligned.m16n8k16.row.col.f32.f16.f16.f32 "
                 "{%0,%1,%2,%3}, {%4,%5,%6,%7}, {%8,%9}, {%0,%1,%2,%3};"
                 : "+f"(c[0]), "+f"(c[1]), "+f"(c[2]), "+f"(c[3])
                 : "r"(a[0]), "r"(a[1]), "r"(a[2]), "r"(a[3]), "r"(b[0]), "r"(b[1]));
}

// ---------------- stage loader: 2 tiles of [128 rows x 128B], 256 threads ----------------
__device__ __forceinline__ void load_stage(
    uint32_t st,
    const __half* __restrict__ A, const __half* __restrict__ W,
    int bm, int bn, int K, int kc0, int tid)
{
#pragma unroll
    for (int i = 0; i < 4; i++) {
        const int lin = i * 256 + tid;
        const int row = lin >> 3;
        const uint32_t q16 = (uint32_t)(lin & 7) * 16u;
        const uint32_t so = SWZ((uint32_t)row * 128u + q16);
        cp16(st + so,          (const char*)A + ((size_t)(bm + row) * K + kc0) * 2 + q16);
        cp16(st + 16384u + so, (const char*)W + ((size_t)(bn + row) * K + kc0) * 2 + q16);
    }
    CP_COMMIT();
}

// ---------------- fused fp16 HMMA GEMM: C = A @ W^T + bias ----------------
//  EPI 0: v = tanh(c)                      -> oh (fp16)
//  EPI 1: outf = c (k1);  v = yin+0.1c     -> oh (fp16 ytmp)
//  EPI 2: v = yin+0.05(k1in+c); outf = v   -> oh (fp16 y_next)
template <int EPI>
__global__ void __launch_bounds__(256, 2) ode_gemm(
    const __half* __restrict__ A, const __half* __restrict__ W,
    const float* __restrict__ bias, int N, int K,
    const float* __restrict__ yin, const float* __restrict__ k1in,
    float* __restrict__ outf, __half* __restrict__ oh)
{
    extern __shared__ char dyn[];
    const uint32_t sb = (smem_u32(dyn) + 1023u) & ~1023u;

    const int tid = threadIdx.x;
    const int wid = tid >> 5, lane = tid & 31;
    const int warp_m = wid >> 2, warp_n = wid & 3;     // 2 x 4 warps, 64x32 warp tile
    const int bm = blockIdx.y * BM, bn = blockIdx.x * BN;

    float acc[4][4][4];
#pragma unroll
    for (int mt = 0; mt < 4; mt++)
#pragma unroll
        for (int nt = 0; nt < 4; nt++)
#pragma unroll
            for (int r = 0; r < 4; r++) acc[mt][nt][r] = 0.f;

    const int nit = K >> 6;
    load_stage(sb,         A, W, bm, bn, K, 0,  tid);
    load_stage(sb + STAGE, A, W, bm, bn, K, BK, tid);

    // per-lane ldmatrix byte offsets (pre-swizzle)
    const uint32_t aOff = (uint32_t)(warp_m * 64 + (lane & 15)) * 128u + (uint32_t)(lane >> 4) * 16u;
    const uint32_t bOff = (uint32_t)(warp_n * 32 + (lane & 7) + ((lane >> 4) << 3)) * 128u
                        + (uint32_t)((lane >> 3) & 1) * 16u;

#pragma unroll 1
    for (int c = 0; c < nit; c++) {
        if (c + 1 < nit) CP_WAIT(1); else CP_WAIT(0);
        __syncthreads();
        // slot (c+2)%3 last held stage c-1, fully consumed before this barrier
        if (c + 2 < nit)
            load_stage(sb + (uint32_t)((c + 2) % NSTAGE) * STAGE, A, W, bm, bn, K,
                       (c + 2) * BK, tid);

        const uint32_t st = sb + (uint32_t)(c % NSTAGE) * STAGE;
#pragma unroll
        for (int ks = 0; ks < 4; ks++) {
            uint32_t ah[4][4], bh[2][4];
#pragma unroll
            for (int mt = 0; mt < 4; mt++) {
                const uint32_t o = SWZ(aOff + (uint32_t)mt * 2048u + (uint32_t)ks * 32u);
                ldsm4(ah[mt][0], ah[mt][1], ah[mt][2], ah[mt][3], st + o);
            }
#pragma unroll
            for (int nb = 0; nb < 2; nb++) {
                const uint32_t o = SWZ(bOff + (uint32_t)nb * 2048u + (uint32_t)ks * 32u);
                ldsm4(bh[nb][0], bh[nb][1], bh[nb][2], bh[nb][3], st + 16384u + o);
            }
#pragma unroll
            for (int mt = 0; mt < 4; mt++)
#pragma unroll
                for (int nt = 0; nt < 4; nt++)
                    mma16816h(acc[mt][nt], ah[mt], &bh[nt >> 1][(nt & 1) * 2]);
        }
    }

    // ---------------- epilogue from register accumulators ----------------
    const int row0 = bm + warp_m * 64 + (lane >> 2);
    const int col0 = bn + warp_n * 32 + (lane & 3) * 2;
#pragma unroll
    for (int mt = 0; mt < 4; mt++)
#pragma unroll
        for (int nt = 0; nt < 4; nt++) {
            const int ccol = col0 + nt * 8;
            const float2 bv = *(const float2*)(bias + ccol);
#pragma unroll
            for (int h = 0; h < 2; h++) {
                const int r = row0 + mt * 16 + 8 * h;
                const size_t idx = (size_t)r * N + ccol;
                float x0 = acc[mt][nt][2 * h]     + bv.x;
                float x1 = acc[mt][nt][2 * h + 1] + bv.y;
                float v0, v1;
                if (EPI == 0) {
                    const float e0 = __expf(2.0f * x0);
                    const float e1 = __expf(2.0f * x1);
                    v0 = 1.0f - __fdividef(2.0f, e0 + 1.0f);
                    v1 = 1.0f - __fdividef(2.0f, e1 + 1.0f);
                } else if (EPI == 1) {
                    *(float2*)(outf + idx) = make_float2(x0, x1);
                    const float2 yv = *(const float2*)(yin + idx);
                    v0 = yv.x + 0.1f * x0;
                    v1 = yv.y + 0.1f * x1;
                } else {
                    const float2 yv = *(const float2*)(yin + idx);
                    const float2 kv = *(const float2*)(k1in + idx);
                    v0 = yv.x + 0.05f * (kv.x + x0);
                    v1 = yv.y + 0.05f * (kv.y + x1);
                    *(float2*)(outf + idx) = make_float2(v0, v1);
                }
                *(__half2*)(oh + idx) = __floats2half2_rn(v0, v1);
            }
        }
}

// ---------------- conversion kernels ----------------
__global__ void to_f16(const float* __restrict__ x, __half* __restrict__ o, int n)
{
    int i = blockIdx.x * blockDim.x + threadIdx.x;
    if (i < n) o[i] = __float2half(x[i]);
}

// W[K,N] row-major -> Wt[N,K] fp16 (K-major B operand)
__global__ void transpose_f16(const float* __restrict__ W, int K, int N,
                              __half* __restrict__ o)
{
    __shared__ float t[32][33];
    const int nx = blockIdx.x * 32 + threadIdx.x;
    const int ky = blockIdx.y * 32 + threadIdx.y;
#pragma unroll
    for (int i = 0; i < 32; i += 8)
        t[threadIdx.y + i][threadIdx.x] = W[(size_t)(ky + i) * N + nx];
    __syncthreads();
    const int on = blockIdx.x * 32 + threadIdx.y;
    const int ok = blockIdx.y * 32 + threadIdx.x;
#pragma unroll
    for (int i = 0; i < 32; i += 8)
        o[(size_t)(on + i) * K + ok] = __float2half(t[threadIdx.x][threadIdx.y + i]);
}

// ---------------- host ----------------
extern "C" void kernel_launch(void* const* d_in, const int* in_sizes, int n_in,
                              void* d_out, int out_size)
{
    const float* y0 = (const float*)d_in[0];
    const float* W1 = (const float*)d_in[1];
    const float* b1 = (const float*)d_in[2];
    const float* W2 = (const float*)d_in[3];
    const float* b2 = (const float*)d_in[4];
    float* yout = (float*)d_out;

    __half *hid16, *y16, *yt16, *w1t, *w2t;
    float *k1f, *yf;
    cudaGetSymbolAddress((void**)&hid16, g_hid16);
    cudaGetSymbolAddress((void**)&y16,   g_y16);
    cudaGetSymbolAddress((void**)&yt16,  g_yt16);
    cudaGetSymbolAddress((void**)&k1f,   g_k1);
    cudaGetSymbolAddress((void**)&yf,    g_yf);
    cudaGetSymbolAddress((void**)&w1t,   g_w1t);
    cudaGetSymbolAddress((void**)&w2t,   g_w2t);

    cudaFuncSetAttribute(ode_gemm<0>, cudaFuncAttributeMaxDynamicSharedMemorySize, SMEM_DYN);
    cudaFuncSetAttribute(ode_gemm<1>, cudaFuncAttributeMaxDynamicSharedMemorySize, SMEM_DYN);
    cudaFuncSetAttribute(ode_gemm<2>, cudaFuncAttributeMaxDynamicSharedMemorySize, SMEM_DYN);

    to_f16<<<(BATCH * DIM + 255) / 256, 256>>>(y0, y16, BATCH * DIM);
    transpose_f16<<<dim3(HID / 32, DIM / 32), dim3(32, 8)>>>(W1, DIM, HID, w1t);
    transpose_f16<<<dim3(DIM / 32, HID / 32), dim3(32, 8)>>>(W2, HID, DIM, w2t);

    const dim3 g1(HID / BN, BATCH / BM);   // (16, 64)
    const dim3 g2(DIM / BN, BATCH / BM);   // (4, 64)

    const float* ycur = y0;
    for (int s = 0; s < NSTEPS; s++) {
        // k1 = f(y): hidden = tanh(y@W1+b1); k1 = hidden@W2+b2; ytmp = y + dt*k1
        ode_gemm<0><<<g1, 256, SMEM_DYN>>>(y16,   w1t, b1, HID, DIM,
                                           nullptr, nullptr, nullptr, hid16);
        ode_gemm<1><<<g2, 256, SMEM_DYN>>>(hid16, w2t, b2, DIM, HID,
                                           ycur, nullptr, k1f, yt16);
        // k2 = f(ytmp); y = y + 0.5*dt*(k1+k2)
        ode_gemm<0><<<g1, 256, SMEM_DYN>>>(yt16,  w1t, b1, HID, DIM,
                                           nullptr, nullptr, nullptr, hid16);
        float* of = (s == NSTEPS - 1) ? yout : yf;
        ode_gemm<2><<<g2, 256, SMEM_DYN>>>(hid16, w2t, b2, DIM, HID,
                                           ycur, k1f, of, y16);
        ycur = yf;
    }
}